// round 3
// baseline (speedup 1.0000x reference)
#include <cuda_runtime.h>
#include <cuda_bf16.h>
#include <cstdint>

// Problem constants (from reference)
#define BB 8
#define SS 4096
#define HH 1024
#define KK 2048   // K = 0.5 * S

// Scratch for logits (no cudaMalloc allowed)
__device__ float g_logits[BB * SS];

// ---------------------------------------------------------------------------
// Pass 1: router GEMV. One warp per token. Coalesced float4 loads.
// hidden: [B*S, H] row-major, w: [H]
// ---------------------------------------------------------------------------
__global__ __launch_bounds__(256) void router_logits_kernel(
    const float* __restrict__ x, const float* __restrict__ w,
    float* __restrict__ logits)
{
    int gw   = (blockIdx.x * blockDim.x + threadIdx.x) >> 5;  // global warp = token
    int lane = threadIdx.x & 31;
    if (gw >= BB * SS) return;

    const float4* xp = reinterpret_cast<const float4*>(x + (size_t)gw * HH);
    const float4* wp = reinterpret_cast<const float4*>(w);

    float acc = 0.0f;
#pragma unroll
    for (int i = 0; i < 8; i++) {                // 8 * 32 lanes * 4 floats = 1024 = H
        int idx = lane + i * 32;                 // coalesced across lanes
        float4 a = xp[idx];
        float4 b = __ldg(&wp[idx]);
        acc = fmaf(a.x, b.x, acc);
        acc = fmaf(a.y, b.y, acc);
        acc = fmaf(a.z, b.z, acc);
        acc = fmaf(a.w, b.w, acc);
    }
#pragma unroll
    for (int o = 16; o; o >>= 1)
        acc += __shfl_xor_sync(0xFFFFFFFFu, acc, o);
    if (lane == 0) logits[gw] = acc;
}

// Monotone float -> orderable uint transform (larger float -> larger uint)
__device__ __forceinline__ uint32_t orderable(float f) {
    uint32_t u = __float_as_uint(f);
    return u ^ ((u >> 31) ? 0xFFFFFFFFu : 0x80000000u);
}

// ---------------------------------------------------------------------------
// Pass 2: per-batch-row exact top-K via 4-pass MSB radix select in SMEM,
// then write router_weights (= sigmoid(logit) * mask) and mask.
// One block per batch row, 256 threads.
// ---------------------------------------------------------------------------
__global__ __launch_bounds__(256) void topk_select_kernel(
    const float* __restrict__ logits, float* __restrict__ out, int out_size)
{
    __shared__ uint32_t keys[SS];      // 16 KB
    __shared__ int      hist[256];     // 1 KB
    __shared__ unsigned char sel[SS];  // 4 KB
    __shared__ uint32_t sh_prefix;
    __shared__ int      sh_kk;         // remaining K within current prefix
    __shared__ int      sh_E;          // count of keys == threshold

    const int b   = blockIdx.x;
    const int tid = threadIdx.x;
    const float* row = logits + b * SS;

    // Load + transform
    for (int s = tid; s < SS; s += 256)
        keys[s] = orderable(row[s]);
    if (tid == 0) { sh_prefix = 0u; sh_kk = KK; }
    __syncthreads();

    // 4 radix passes, MSB first, descending (top-K)
#pragma unroll
    for (int pass = 0; pass < 4; pass++) {
        const int shift = 24 - pass * 8;
        // prefix mask covers the digits already fixed
        const uint32_t pmask = (pass == 0) ? 0u : (0xFFFFFFFFu << (shift + 8));

        hist[tid] = 0;
        __syncthreads();

        const uint32_t prefix = sh_prefix;
        for (int s = tid; s < SS; s += 256) {
            uint32_t k = keys[s];
            if ((k & pmask) == prefix)
                atomicAdd(&hist[(k >> shift) & 0xFF], 1);
        }
        __syncthreads();

        if (tid == 0) {
            int kk  = sh_kk;
            int acc = 0;
            int d   = 255;
            for (; d >= 0; d--) {
                int h = hist[d];
                if (acc + h >= kk) break;
                acc += h;
            }
            sh_prefix = prefix | ((uint32_t)d << shift);
            sh_kk = kk - acc;          // how many to take from this digit bucket
            sh_E  = hist[d];           // equals-count (valid meaning on final pass)
        }
        __syncthreads();
    }

    const uint32_t thresh = sh_prefix;   // exact K-th largest key
    const int T = sh_kk;                 // quota of equals to accept
    const int E = sh_E;                  // number of equals

    // Common case: accept all strictly-greater, and all equals iff E == T
    const unsigned char take_eq = (E <= T) ? 1 : 0;
    for (int s = tid; s < SS; s += 256) {
        uint32_t k = keys[s];
        sel[s] = (k > thresh) ? 1 : ((k == thresh) ? take_eq : 0);
    }
    __syncthreads();

    // Rare tie path: accept only the first T equals by index (matches
    // jax.lax.top_k stable lowest-index-first behavior). Serial, but E > T
    // essentially never happens with continuous random inputs.
    if (E > T) {
        if (tid == 0) {
            int taken = 0;
            for (int s = 0; s < SS; s++) {
                if (keys[s] == thresh) {
                    sel[s] = (taken < T) ? 1 : 0;
                    taken++;
                }
            }
        }
        __syncthreads();
    }

    // Emit outputs: weights = sigmoid(logit) * mask; mask as 0/1 float.
    const int base = b * SS;
    const bool has_mask_half = (out_size >= 2 * BB * SS);
    for (int s = tid; s < SS; s += 256) {
        float logit = row[s];
        float score = 1.0f / (1.0f + expf(-logit));
        unsigned char m = sel[s];
        out[base + s] = m ? score : 0.0f;
        if (has_mask_half)
            out[BB * SS + base + s] = m ? 1.0f : 0.0f;
    }
}

extern "C" void kernel_launch(void* const* d_in, const int* in_sizes, int n_in,
                              void* d_out, int out_size)
{
    const float* hidden = (const float*)d_in[0];   // [B,S,H] f32
    const float* w      = (const float*)d_in[1];   // [H] f32
    float* out = (float*)d_out;

    float* logits = nullptr;
    cudaGetSymbolAddress((void**)&logits, g_logits);

    // Pass 1: 1 warp/token, 8 warps/block -> 4096 blocks
    const int tokens = BB * SS;
    router_logits_kernel<<<tokens / 8, 256>>>(hidden, w, logits);

    // Pass 2: one block per batch row
    topk_select_kernel<<<BB, 256>>>(logits, out, out_size);
}

// round 4
// speedup vs baseline: 1.6439x; 1.6439x over previous
#include <cuda_runtime.h>
#include <cuda_bf16.h>
#include <cstdint>

#define BB 8
#define SS 4096
#define HH 1024
#define KK 2048   // K = 0.5 * S

__device__ float g_logits[BB * SS];

// ---------------------------------------------------------------------------
// Pass 1: router GEMV. One warp per 2 tokens (MLP=16 float4 loads in flight).
// ---------------------------------------------------------------------------
__global__ __launch_bounds__(256) void router_logits_kernel(
    const float* __restrict__ x, const float* __restrict__ w,
    float* __restrict__ logits)
{
    int gw   = (blockIdx.x * blockDim.x + threadIdx.x) >> 5;
    int lane = threadIdx.x & 31;
    int r0   = gw * 2;
    if (r0 >= BB * SS) return;

    const float4* xp0 = reinterpret_cast<const float4*>(x + (size_t)r0 * HH);
    const float4* xp1 = xp0 + (HH / 4);
    const float4* wp  = reinterpret_cast<const float4*>(w);

    float a0 = 0.0f, a1 = 0.0f;
#pragma unroll
    for (int i = 0; i < 8; i++) {                 // 8 * 32 * 4 = 1024 = H
        int idx = lane + i * 32;
        float4 wv = __ldg(&wp[idx]);
        float4 u  = xp0[idx];
        float4 t  = xp1[idx];
        a0 = fmaf(u.x, wv.x, a0); a0 = fmaf(u.y, wv.y, a0);
        a0 = fmaf(u.z, wv.z, a0); a0 = fmaf(u.w, wv.w, a0);
        a1 = fmaf(t.x, wv.x, a1); a1 = fmaf(t.y, wv.y, a1);
        a1 = fmaf(t.z, wv.z, a1); a1 = fmaf(t.w, wv.w, a1);
    }
#pragma unroll
    for (int o = 16; o; o >>= 1) {
        a0 += __shfl_xor_sync(0xFFFFFFFFu, a0, o);
        a1 += __shfl_xor_sync(0xFFFFFFFFu, a1, o);
    }
    if (lane == 0) {
        logits[r0]     = a0;
        logits[r0 + 1] = a1;
    }
}

__device__ __forceinline__ uint32_t orderable(float f) {
    uint32_t u = __float_as_uint(f);
    return u ^ ((u >> 31) ? 0xFFFFFFFFu : 0x80000000u);
}

// ---------------------------------------------------------------------------
// Pass 2: per-row exact top-K via 4-pass MSB radix select.
// 1024 threads/block, 4 elements/thread held in registers.
// Digit selection done by warp 0 with a shfl suffix-scan (parallel, ~300cyc).
// ---------------------------------------------------------------------------
__global__ __launch_bounds__(1024) void topk_select_kernel(
    const float* __restrict__ logits, float* __restrict__ out, int out_size)
{
    __shared__ uint32_t skeys[SS];   // used only for the rare tie path
    __shared__ int      hist[256];
    __shared__ uint32_t sh_prefix;
    __shared__ int      sh_kk;       // remaining quota within current prefix
    __shared__ int      sh_E;        // count of keys == threshold (final pass)
    __shared__ int      sh_cut;      // last accepted index among equals

    const int b   = blockIdx.x;
    const int tid = threadIdx.x;
    const float* row = logits + b * SS;

    float    v[4];
    uint32_t k[4];
#pragma unroll
    for (int i = 0; i < 4; i++) {
        int s = tid + i * 1024;
        v[i] = row[s];
        k[i] = orderable(v[i]);
        skeys[s] = k[i];
    }
    if (tid == 0) { sh_prefix = 0u; sh_kk = KK; }

#pragma unroll
    for (int pass = 0; pass < 4; pass++) {
        const int shift = 24 - pass * 8;
        const uint32_t pmask = (pass == 0) ? 0u : (0xFFFFFFFFu << (shift + 8));

        if (tid < 256) hist[tid] = 0;
        __syncthreads();                 // also orders sh_prefix/sh_kk writes

        const uint32_t prefix = sh_prefix;
#pragma unroll
        for (int i = 0; i < 4; i++)
            if ((k[i] & pmask) == prefix)
                atomicAdd(&hist[(k[i] >> shift) & 0xFF], 1);
        __syncthreads();

        // warp 0: parallel descending suffix-scan over 256 bins, 8 bins/lane
        if (tid < 32) {
            const int kk   = sh_kk;
            const int lane = tid;
            int h[8];
            int part = 0;
#pragma unroll
            for (int j = 0; j < 8; j++) {
                h[j] = hist[255 - (lane * 8 + j)];
                part += h[j];
            }
            // inclusive scan across lanes (lane 0 = highest digits)
            int inc = part;
#pragma unroll
            for (int o = 1; o < 32; o <<= 1) {
                int t = __shfl_up_sync(0xFFFFFFFFu, inc, o);
                if (lane >= o) inc += t;
            }
            const int excl = inc - part; // keys in digits strictly above my chunk
            if (excl < kk && excl + part >= kk) {   // unique crossing lane
                int acc = excl;
#pragma unroll
                for (int j = 0; j < 8; j++) {
                    if (acc + h[j] >= kk) {
                        int d = 255 - (lane * 8 + j);
                        sh_prefix = prefix | ((uint32_t)d << shift);
                        sh_kk = kk - acc;
                        sh_E  = h[j];
                        break;
                    }
                    acc += h[j];
                }
            }
        }
        __syncthreads();
    }

    const uint32_t thresh = sh_prefix;  // exact K-th largest key
    const int T = sh_kk;                // equals quota (>=1)
    const int E = sh_E;                 // equals count (>=T)

    if (tid == 0) {
        if (E > T) {
            // rare: accept only first T equals by index (lax.top_k stability)
            int taken = 0, cut = -1;
            for (int s = 0; s < SS; s++) {
                if (skeys[s] == thresh) {
                    if (++taken == T) { cut = s; break; }
                }
            }
            sh_cut = cut;
        } else {
            sh_cut = SS;   // accept all equals
        }
    }
    __syncthreads();
    const int cut = sh_cut;

    const int  base = b * SS;
    const bool has_mask_half = (out_size >= 2 * BB * SS);
#pragma unroll
    for (int i = 0; i < 4; i++) {
        int s = tid + i * 1024;
        bool m = (k[i] > thresh) || (k[i] == thresh && s <= cut);
        float score = 1.0f / (1.0f + expf(-v[i]));
        out[base + s] = m ? score : 0.0f;
        if (has_mask_half)
            out[BB * SS + base + s] = m ? 1.0f : 0.0f;
    }
}

extern "C" void kernel_launch(void* const* d_in, const int* in_sizes, int n_in,
                              void* d_out, int out_size)
{
    const float* hidden = (const float*)d_in[0];
    const float* w      = (const float*)d_in[1];
    float* out = (float*)d_out;

    float* logits = nullptr;
    cudaGetSymbolAddress((void**)&logits, g_logits);

    const int tokens = BB * SS;
    router_logits_kernel<<<tokens / 16, 256>>>(hidden, w, logits);  // 2 tokens/warp
    topk_select_kernel<<<BB, 1024>>>(logits, out, out_size);
}